// round 1
// baseline (speedup 1.0000x reference)
#include <cuda_runtime.h>

#define NN 4096
#define DIM 64
#define INF_V 1e10f
#define HB 128            // rows per DP block
#define NBLK (NN/HB)      // 32
#define CCHUNK 64         // boundary-row publish granularity (columns)

// Scratch (static __device__ arrays: allocation-free per harness rules)
__device__ float g_D[(size_t)NN * NN];    // 64 MB cost matrix
__device__ float g_xn[NN];
__device__ float g_yn[NN];
__device__ float g_bnd[NBLK][NN];         // bottom boundary row of each block
__device__ int   g_prog[NBLK];            // columns published per block

// ---------------- norms ----------------
__global__ void norms_kernel(const float* __restrict__ x, const float* __restrict__ y) {
    int w = (blockIdx.x * blockDim.x + threadIdx.x) >> 5;
    int lane = threadIdx.x & 31;
    if (w >= 2 * NN) return;
    const float* src = (w < NN) ? x : y;
    int row = (w < NN) ? w : w - NN;
    float a = src[row * DIM + lane];
    float b = src[row * DIM + 32 + lane];
    float s = a * a + b * b;
    #pragma unroll
    for (int o = 16; o; o >>= 1) s += __shfl_xor_sync(0xffffffffu, s, o);
    if (lane == 0) { if (w < NN) g_xn[row] = s; else g_yn[row] = s; }
}

// ---------------- D = |x|^2 + |y|^2 - 2 x.y  (64x64 tile per block) ----------------
__global__ void dmat_kernel(const float* __restrict__ x, const float* __restrict__ y) {
    __shared__ float xs[64][65];
    __shared__ float ys[64][65];
    int tx = threadIdx.x, ty = threadIdx.y;
    int tid = ty * 16 + tx;
    int rb = blockIdx.y * 64, cb = blockIdx.x * 64;

    for (int i = tid; i < 64 * 64; i += 256) {
        int rr = i >> 6, kk = i & 63;
        xs[rr][kk] = x[(rb + rr) * DIM + kk];
        ys[rr][kk] = y[(cb + rr) * DIM + kk];
    }
    __syncthreads();

    float acc[4][4] = {};
    #pragma unroll
    for (int k = 0; k < 64; k++) {
        float xv[4], yv[4];
        #pragma unroll
        for (int i = 0; i < 4; i++) xv[i] = xs[ty + 16 * i][k];
        #pragma unroll
        for (int j = 0; j < 4; j++) yv[j] = ys[tx + 16 * j][k];
        #pragma unroll
        for (int i = 0; i < 4; i++)
            #pragma unroll
            for (int j = 0; j < 4; j++)
                acc[i][j] += xv[i] * yv[j];
    }

    #pragma unroll
    for (int i = 0; i < 4; i++) {
        int r = rb + ty + 16 * i;
        float xnr = g_xn[r];
        #pragma unroll
        for (int j = 0; j < 4; j++) {
            int c = cb + tx + 16 * j;
            g_D[(size_t)r * NN + c] = xnr + g_yn[c] - 2.0f * acc[i][j];
        }
    }
}

// ---------------- reset progress flags (graph replays reuse state) ----------------
__global__ void init_kernel() {
    if (threadIdx.x < NBLK) g_prog[threadIdx.x] = 0;
}

// ---------------- DP wavefront ----------------
__device__ __forceinline__ int ld_acq(const int* p) {
    int v;
    asm volatile("ld.acquire.gpu.u32 %0, [%1];" : "=r"(v) : "l"(p) : "memory");
    return v;
}
__device__ __forceinline__ void st_rel(int* p, int v) {
    asm volatile("st.release.gpu.u32 [%0], %1;" :: "l"(p), "r"(v) : "memory");
}

__global__ void __launch_bounds__(HB, 1) dp_kernel(float* __restrict__ out) {
    __shared__ float buf[3][HB];
    __shared__ float topb[CCHUNK + 2];

    const int b = blockIdx.x;
    const int L = threadIdx.x;
    const int r = b * HB + L;
    const float* __restrict__ Drow = g_D + (size_t)r * NN;
    float* mybnd = g_bnd[b];
    const float* upbnd = (b > 0) ? g_bnd[b - 1] : (const float*)0;

    buf[0][L] = INF_V; buf[1][L] = INF_V; buf[2][L] = INF_V;
    __syncthreads();

    float left = INF_V;          // v[r][c-1]
    float* prev  = buf[2];       // values at step t-1 (by thread index)
    float* prev2 = buf[1];       // values at step t-2
    float* nxt   = buf[0];       // write target at step t

    const int T = NN + HB - 1;   // 4223 anti-diagonal steps
    #pragma unroll 1
    for (int t = 0; t < T; t++) {
        // Stage the boundary row chunk from the block above
        if (b > 0 && t < NN && (t & (CCHUNK - 1)) == 0) {
            if (L == 0) {
                int need = t + CCHUNK; if (need > NN) need = NN;
                while (ld_acq(&g_prog[b - 1]) < need) { }
            }
            __syncthreads();
            if (L <= CCHUNK) {
                int col = t - 1 + L;                 // window covers cols [t-1, t+CCHUNK-1]
                topb[L] = (col >= 0) ? upbnd[col] : INF_V;
            }
            __syncthreads();
        }

        const int c = t - L;
        const bool active = (c >= 0) && (c < NN);
        float v;
        if (active) {
            float up, dg;
            if (L == 0) {
                if (b == 0) { up = INF_V; dg = (c == 0) ? 0.0f : INF_V; }
                else { int tc = t & (CCHUNK - 1); up = topb[tc + 1]; dg = topb[tc]; }
            } else {
                up = prev[L - 1];
                dg = prev2[L - 1];
            }
            float cost = __ldg(&Drow[c]);
            float m = fminf(up, fminf(left, dg));
            float s = __expf(m - up) + __expf(m - left) + __expf(m - dg);
            v = cost + m - __logf(s);
            left = v;
        }
        // (reads of prev2-buffer from step t-1 are separated from this write by
        //  the end-of-step barrier of step t-1, so one barrier per step suffices)
        if (active) {
            nxt[L] = v;
            if (L == HB - 1 && b < NBLK - 1) {
                mybnd[c] = v;
                if (((c + 1) & (CCHUNK - 1)) == 0) {
                    __threadfence();
                    st_rel(&g_prog[b], c + 1);
                }
            }
        }
        __syncthreads();
        // rotate buffers
        float* tmp = prev2; prev2 = prev; prev = nxt; nxt = tmp;
    }

    if (b == NBLK - 1 && L == HB - 1) out[0] = left;   // dp[4096][4096]
}

extern "C" void kernel_launch(void* const* d_in, const int* in_sizes, int n_in,
                              void* d_out, int out_size) {
    const float* x = (const float*)d_in[0];
    const float* y = (const float*)d_in[1];
    float* out = (float*)d_out;

    norms_kernel<<<(2 * NN * 32) / 256, 256>>>(x, y);
    dim3 gD(NN / 64, NN / 64);
    dim3 bD(16, 16);
    dmat_kernel<<<gD, bD>>>(x, y);
    init_kernel<<<1, 32>>>();
    dp_kernel<<<NBLK, HB>>>(out);
}